// round 1
// baseline (speedup 1.0000x reference)
#include <cuda_runtime.h>
#include <cuda_bf16.h>
#include <math.h>

// ---------------- problem constants ----------------
#define NN    50000
#define EE    400000
#define GG    256
#define FIN   79
#define DD    400
#define BN_EPS 1e-5f

// ---------------- scratch (static device globals; no runtime alloc) ----------
__device__ float g_bufA[(size_t)NN * DD];   // 80 MB
__device__ float g_bufB[(size_t)NN * DD];   // 80 MB
__device__ float g_bufC[(size_t)NN * DD];   // 80 MB
__device__ float g_poolMax[GG * DD];
__device__ float g_poolSum[GG * DD];
__device__ float g_cnt[GG];
__device__ float g_alpha1[DD], g_beta1[DD], g_alpha2[DD], g_beta2[DD];

// ---------------- small kernels ----------------

// fold bias + BN into per-column alpha/beta:  y = alpha*acc + beta
__global__ void make_ab_kernel(const float* __restrict__ b1,
                               const float* __restrict__ g,
                               const float* __restrict__ bb,
                               const float* __restrict__ m,
                               const float* __restrict__ v,
                               float* __restrict__ alpha,
                               float* __restrict__ beta) {
    int c = blockIdx.x * blockDim.x + threadIdx.x;
    if (c >= DD) return;
    float a = g[c] * rsqrtf(v[c] + BN_EPS);
    alpha[c] = a;
    beta[c]  = (b1[c] - m[c]) * a + bb[c];
}

// z = (1+eps)*h  (eps is a device scalar)
__global__ void scale_init_kernel(const float* __restrict__ h,
                                  const float* __restrict__ eps,
                                  float* __restrict__ z, int total) {
    int i = blockIdx.x * blockDim.x + threadIdx.x;
    if (i >= total) return;
    z[i] = (1.0f + eps[0]) * h[i];
}

// z[dst[e]] += h[src[e]]   (one thread per (edge, feature))
template <int D_>
__global__ void scatter_add_kernel(const float* __restrict__ h,
                                   const int* __restrict__ src,
                                   const int* __restrict__ dst,
                                   float* __restrict__ z, int total) {
    int idx = blockIdx.x * blockDim.x + threadIdx.x;
    if (idx >= total) return;
    int e = idx / D_;
    int f = idx - e * D_;
    float val = h[src[e] * D_ + f];
    atomicAdd(&z[dst[e] * D_ + f], val);
}

// ---------------- tiled SGEMM with fused epilogue ----------------
// C[n x 400] = act( alpha .* (A[n x K] @ W[K x 400]) + beta )
// ACT: 0 = relu, 1 = tanh. alpha may be null (treated as 1).
#define BM 64
#define BN_T 80
#define BK 16

template <int ACT>
__global__ __launch_bounds__(256) void gemm_epi_kernel(
    const float* __restrict__ A, const float* __restrict__ W,
    const float* __restrict__ alpha, const float* __restrict__ beta,
    float* __restrict__ C, int n, int K) {
    __shared__ float As[BK][BM + 1];   // +1 pad: conflict-reduced transposed store
    __shared__ float Bs[BK][BN_T];

    int tid = threadIdx.x;
    int tx  = tid & 15;    // column group 0..15
    int ty  = tid >> 4;    // row group 0..15
    int m0  = blockIdx.x * BM;
    int c0  = blockIdx.y * BN_T;

    float acc[4][5];
#pragma unroll
    for (int i = 0; i < 4; i++)
#pragma unroll
        for (int j = 0; j < 5; j++) acc[i][j] = 0.0f;

    for (int kt = 0; kt < K; kt += BK) {
        // load A tile (64 x 16), coalesced: 16 consecutive threads read 16
        // consecutive k of one row
#pragma unroll
        for (int l = 0; l < 4; l++) {
            int e  = tid + l * 256;
            int ar = e >> 4;         // 0..63
            int ak = e & 15;         // 0..15
            int gr = m0 + ar;
            int gk = kt + ak;
            float vv = 0.0f;
            if (gr < n && gk < K) vv = A[(size_t)gr * K + gk];
            As[ak][ar] = vv;
        }
        // load B tile (16 x 80), coalesced along columns
#pragma unroll
        for (int l = 0; l < 5; l++) {
            int e  = tid + l * 256;
            int bk = e / BN_T;
            int bc = e - bk * BN_T;
            int gk = kt + bk;
            float vv = 0.0f;
            if (gk < K) vv = W[(size_t)gk * DD + c0 + bc];
            Bs[bk][bc] = vv;
        }
        __syncthreads();

#pragma unroll
        for (int k = 0; k < BK; k++) {
            float a0 = As[k][ty * 4 + 0];
            float a1 = As[k][ty * 4 + 1];
            float a2 = As[k][ty * 4 + 2];
            float a3 = As[k][ty * 4 + 3];
            float b[5];
#pragma unroll
            for (int j = 0; j < 5; j++) b[j] = Bs[k][tx + 16 * j];
#pragma unroll
            for (int j = 0; j < 5; j++) {
                acc[0][j] = fmaf(a0, b[j], acc[0][j]);
                acc[1][j] = fmaf(a1, b[j], acc[1][j]);
                acc[2][j] = fmaf(a2, b[j], acc[2][j]);
                acc[3][j] = fmaf(a3, b[j], acc[3][j]);
            }
        }
        __syncthreads();
    }

    // epilogue
#pragma unroll
    for (int j = 0; j < 5; j++) {
        int c  = c0 + tx + 16 * j;
        float al = alpha ? alpha[c] : 1.0f;
        float be = beta[c];
#pragma unroll
        for (int i = 0; i < 4; i++) {
            int r = m0 + ty * 4 + i;
            if (r < n) {
                float vv = acc[i][j] * al + be;
                if (ACT == 0) vv = fmaxf(vv, 0.0f);
                else          vv = tanhf(vv);
                C[(size_t)r * DD + c] = vv;
            }
        }
    }
}

// ---------------- pooling ----------------

__global__ void pool_init_kernel(float* pmax, float* psum, float* cnt) {
    int i = blockIdx.x * blockDim.x + threadIdx.x;
    if (i < GG * DD) {
        pmax[i] = __int_as_float(0xff800000);  // -inf
        psum[i] = 0.0f;
    }
    if (i < GG) cnt[i] = 0.0f;
}

__device__ __forceinline__ void atomicMaxFloat(float* addr, float val) {
    int* ai = (int*)addr;
    int old = *ai;
    while (__int_as_float(old) < val) {
        int assumed = old;
        old = atomicCAS(ai, assumed, __float_as_int(val));
        if (old == assumed) break;
    }
}

__global__ void pool_scatter_kernel(const float* __restrict__ h,
                                    const int* __restrict__ batch,
                                    float* pmax, float* psum, float* cnt) {
    int idx = blockIdx.x * blockDim.x + threadIdx.x;
    if (idx >= NN * DD) return;
    int node = idx / DD;
    int f    = idx - node * DD;
    int gidx = batch[node];
    float v  = h[idx];
    atomicAdd(&psum[gidx * DD + f], v);
    atomicMaxFloat(&pmax[gidx * DD + f], v);
    if (f == 0) atomicAdd(&cnt[gidx], 1.0f);
}

__global__ void final_out_kernel(const float* __restrict__ pmax,
                                 const float* __restrict__ psum,
                                 const float* __restrict__ cnt,
                                 const float* __restrict__ w,
                                 const float* __restrict__ b,
                                 float* __restrict__ out) {
    int g   = blockIdx.x;
    int tid = threadIdx.x;
    float invc = 1.0f / fmaxf(cnt[g], 1.0f);
    float s = 0.0f;
    for (int j = tid; j < DD; j += blockDim.x) {
        s += pmax[g * DD + j] * w[j] + psum[g * DD + j] * invc * w[DD + j];
    }
#pragma unroll
    for (int o = 16; o > 0; o >>= 1) s += __shfl_down_sync(0xffffffffu, s, o);
    __shared__ float sh[4];
    if ((tid & 31) == 0) sh[tid >> 5] = s;
    __syncthreads();
    if (tid == 0) {
        float t = sh[0] + sh[1] + sh[2] + sh[3];
        out[g] = t + b[0];
    }
}

// ---------------- host-side orchestration ----------------

static inline int ceil_div(int a, int b) { return (a + b - 1) / b; }

extern "C" void kernel_launch(void* const* d_in, const int* in_sizes, int n_in,
                              void* d_out, int out_size) {
    const float* x     = (const float*)d_in[0];
    const int*   ei    = (const int*)d_in[1];
    const int*   src   = ei;
    const int*   dst   = ei + EE;
    const int*   batch = (const int*)d_in[2];

    // num_graphs may or may not appear as a size-1 input
    int base = (in_sizes[3] == 1) ? 4 : 3;

    const float* mlp1_w1   = (const float*)d_in[base + 0];
    const float* mlp1_b1   = (const float*)d_in[base + 1];
    const float* mlp1_bn_g = (const float*)d_in[base + 2];
    const float* mlp1_bn_b = (const float*)d_in[base + 3];
    const float* mlp1_bn_m = (const float*)d_in[base + 4];
    const float* mlp1_bn_v = (const float*)d_in[base + 5];
    const float* mlp1_w2   = (const float*)d_in[base + 6];
    const float* mlp1_b2   = (const float*)d_in[base + 7];
    const float* mlp2_w1   = (const float*)d_in[base + 8];
    const float* mlp2_b1   = (const float*)d_in[base + 9];
    const float* mlp2_bn_g = (const float*)d_in[base + 10];
    const float* mlp2_bn_b = (const float*)d_in[base + 11];
    const float* mlp2_bn_m = (const float*)d_in[base + 12];
    const float* mlp2_bn_v = (const float*)d_in[base + 13];
    const float* mlp2_w2   = (const float*)d_in[base + 14];
    const float* mlp2_b2   = (const float*)d_in[base + 15];
    const float* out1_w    = (const float*)d_in[base + 16];
    const float* out1_b    = (const float*)d_in[base + 17];
    const float* out2_w    = (const float*)d_in[base + 18];
    const float* out2_b    = (const float*)d_in[base + 19];
    const float* out3_w    = (const float*)d_in[base + 20];
    const float* out3_b    = (const float*)d_in[base + 21];
    const float* out_w     = (const float*)d_in[base + 22];
    const float* out_b     = (const float*)d_in[base + 23];
    const float* eps1      = (const float*)d_in[base + 24];
    const float* eps2      = (const float*)d_in[base + 25];
    const float* eps3      = (const float*)d_in[base + 26];

    float* out = (float*)d_out;

    float *bufA, *bufB, *bufC, *pmax, *psum, *cnt;
    float *alpha1, *beta1, *alpha2, *beta2;
    cudaGetSymbolAddress((void**)&bufA, g_bufA);
    cudaGetSymbolAddress((void**)&bufB, g_bufB);
    cudaGetSymbolAddress((void**)&bufC, g_bufC);
    cudaGetSymbolAddress((void**)&pmax, g_poolMax);
    cudaGetSymbolAddress((void**)&psum, g_poolSum);
    cudaGetSymbolAddress((void**)&cnt,  g_cnt);
    cudaGetSymbolAddress((void**)&alpha1, g_alpha1);
    cudaGetSymbolAddress((void**)&beta1,  g_beta1);
    cudaGetSymbolAddress((void**)&alpha2, g_alpha2);
    cudaGetSymbolAddress((void**)&beta2,  g_beta2);

    dim3 gemm_grid(ceil_div(NN, BM), DD / BN_T);  // (782, 5)

    // fold BN params
    make_ab_kernel<<<ceil_div(DD, 128), 128>>>(mlp1_b1, mlp1_bn_g, mlp1_bn_b,
                                               mlp1_bn_m, mlp1_bn_v, alpha1, beta1);
    make_ab_kernel<<<ceil_div(DD, 128), 128>>>(mlp2_b1, mlp2_bn_g, mlp2_bn_b,
                                               mlp2_bn_m, mlp2_bn_v, alpha2, beta2);

    // ---------- layer 1 (input dim 79) ----------
    {
        int tot = NN * FIN;
        scale_init_kernel<<<ceil_div(tot, 256), 256>>>(x, eps1, bufA, tot);
        int etot = EE * FIN;
        scatter_add_kernel<FIN><<<ceil_div(etot, 256), 256>>>(x, src, dst, bufA, etot);
        gemm_epi_kernel<0><<<gemm_grid, 256>>>(bufA, mlp1_w1, alpha1, beta1, bufB, NN, FIN);
        gemm_epi_kernel<0><<<gemm_grid, 256>>>(bufB, mlp1_w2, nullptr, mlp1_b2, bufA, NN, DD);
        gemm_epi_kernel<1><<<gemm_grid, 256>>>(bufA, out1_w, nullptr, out1_b, bufB, NN, DD);
    }
    // ---------- layer 2 ----------
    {
        int tot = NN * DD;
        scale_init_kernel<<<ceil_div(tot, 256), 256>>>(bufB, eps2, bufA, tot);
        int etot = EE * DD;
        scatter_add_kernel<DD><<<ceil_div(etot, 256), 256>>>(bufB, src, dst, bufA, etot);
        gemm_epi_kernel<0><<<gemm_grid, 256>>>(bufA, mlp2_w1, alpha2, beta2, bufC, NN, DD);
        gemm_epi_kernel<0><<<gemm_grid, 256>>>(bufC, mlp2_w2, nullptr, mlp2_b2, bufA, NN, DD);
        gemm_epi_kernel<1><<<gemm_grid, 256>>>(bufA, out2_w, nullptr, out2_b, bufB, NN, DD);
    }
    // ---------- layer 3 (reuses mlp2 weights) ----------
    {
        int tot = NN * DD;
        scale_init_kernel<<<ceil_div(tot, 256), 256>>>(bufB, eps3, bufA, tot);
        int etot = EE * DD;
        scatter_add_kernel<DD><<<ceil_div(etot, 256), 256>>>(bufB, src, dst, bufA, etot);
        gemm_epi_kernel<0><<<gemm_grid, 256>>>(bufA, mlp2_w1, alpha2, beta2, bufC, NN, DD);
        gemm_epi_kernel<0><<<gemm_grid, 256>>>(bufC, mlp2_w2, nullptr, mlp2_b2, bufA, NN, DD);
        gemm_epi_kernel<1><<<gemm_grid, 256>>>(bufA, out3_w, nullptr, out3_b, bufB, NN, DD);
    }
    // ---------- pooling + final projection ----------
    pool_init_kernel<<<ceil_div(GG * DD, 256), 256>>>(pmax, psum, cnt);
    pool_scatter_kernel<<<ceil_div(NN * DD, 256), 256>>>(bufB, batch, pmax, psum, cnt);
    final_out_kernel<<<GG, 128>>>(pmax, psum, cnt, out_w, out_b, out);
    (void)n_in; (void)out_size;
}

// round 3
// speedup vs baseline: 2.1246x; 2.1246x over previous
#include <cuda_runtime.h>
#include <cuda_bf16.h>
#include <cstdint>
#include <math.h>

// ================= problem constants =================
#define NN    50000
#define EE    400000
#define GG    256
#define FIN   79
#define DD    400
#define BN_EPS 1e-5f

#define NMATS  7
#define WPITCH 416            // padded K pitch for staged weights (13 * 32)
#define APITCH 416            // padded K pitch for activation planes
#define AP_U32 (APITCH / 2)   // 208 u32 per row

// ================= scratch (device globals; zero-initialized) ============
__device__ float g_bufA[(size_t)NN * DD];
__device__ float g_bufB[(size_t)NN * DD];
__device__ __align__(16) __nv_bfloat16 g_P0hi[(size_t)NN * APITCH];
__device__ __align__(16) __nv_bfloat16 g_P0lo[(size_t)NN * APITCH];
__device__ __align__(16) __nv_bfloat16 g_P1hi[(size_t)NN * APITCH];
__device__ __align__(16) __nv_bfloat16 g_P1lo[(size_t)NN * APITCH];
__device__ __align__(16) __nv_bfloat16 g_Whi[(size_t)NMATS * DD * WPITCH];
__device__ __align__(16) __nv_bfloat16 g_Wlo[(size_t)NMATS * DD * WPITCH];
__device__ float g_alpha1[DD], g_beta1[DD], g_alpha2[DD], g_beta2[DD];

// ================= helpers =================
__device__ __forceinline__ uint32_t smem_to_u32(const void* p) {
    uint32_t a;
    asm("{ .reg .u64 t; cvta.to.shared.u64 t, %1; cvt.u32.u64 %0, t; }"
        : "=r"(a) : "l"(p));
    return a;
}

__device__ __forceinline__ void cp16(uint32_t saddr, const void* gptr, bool valid) {
    int sz = valid ? 16 : 0;
    asm volatile("cp.async.cg.shared.global [%0], [%1], 16, %2;"
                 :: "r"(saddr), "l"(gptr), "r"(sz));
}
#define CP_COMMIT() asm volatile("cp.async.commit_group;")
#define CP_WAIT(n)  asm volatile("cp.async.wait_group %0;" :: "n"(n))

#define LDSM4(R, addr) \
    asm volatile("ldmatrix.sync.aligned.m8n8.x4.shared.b16 {%0,%1,%2,%3}, [%4];" \
        : "=r"((R)[0]), "=r"((R)[1]), "=r"((R)[2]), "=r"((R)[3]) : "r"(addr))

#define LDSM2(R, addr) \
    asm volatile("ldmatrix.sync.aligned.m8n8.x2.shared.b16 {%0,%1}, [%2];" \
        : "=r"((R)[0]), "=r"((R)[1]) : "r"(addr))

__device__ __forceinline__ void mma_bf16(float* d, const uint32_t* a, const uint32_t* b) {
    asm volatile(
        "mma.sync.aligned.m16n8k16.row.col.f32.bf16.bf16.f32 "
        "{%0,%1,%2,%3}, {%4,%5,%6,%7}, {%8,%9}, {%0,%1,%2,%3};"
        : "+f"(d[0]), "+f"(d[1]), "+f"(d[2]), "+f"(d[3])
        : "r"(a[0]), "r"(a[1]), "r"(a[2]), "r"(a[3]), "r"(b[0]), "r"(b[1]));
}

__device__ __forceinline__ uint32_t pack_bf16x2(float x, float y) {
    __nv_bfloat16 hx = __float2bfloat16(x);
    __nv_bfloat16 hy = __float2bfloat16(y);
    return ((uint32_t)*(uint16_t*)&hy << 16) | *(uint16_t*)&hx;
}

// ================= small kernels =================

__global__ void make_ab_kernel(const float* __restrict__ b1,
                               const float* __restrict__ g,
                               const float* __restrict__ bb,
                               const float* __restrict__ m,
                               const float* __restrict__ v,
                               float* __restrict__ alpha,
                               float* __restrict__ beta) {
    int c = blockIdx.x * blockDim.x + threadIdx.x;
    if (c >= DD) return;
    float a = g[c] * rsqrtf(v[c] + BN_EPS);
    alpha[c] = a;
    beta[c]  = (b1[c] - m[c]) * a + bb[c];
}

// Stage W^T as bf16 hi/lo planes: layout [mat][n=400][k padded to 416]
__global__ void stage_w_kernel(const float* __restrict__ w0, const float* __restrict__ w1,
                               const float* __restrict__ w2, const float* __restrict__ w3,
                               const float* __restrict__ w4, const float* __restrict__ w5,
                               const float* __restrict__ w6) {
    int idx = blockIdx.x * blockDim.x + threadIdx.x;
    const int per_mat = DD * WPITCH;
    if (idx >= NMATS * per_mat) return;
    int m = idx / per_mat;
    int r = idx - m * per_mat;
    int n = r / WPITCH;
    int k = r - n * WPITCH;
    int Km = (m == 0) ? FIN : DD;
    const float* W;
    switch (m) {
        case 0: W = w0; break; case 1: W = w1; break; case 2: W = w2; break;
        case 3: W = w3; break; case 4: W = w4; break; case 5: W = w5; break;
        default: W = w6; break;
    }
    float val = (k < Km) ? W[(size_t)k * DD + n] : 0.0f;
    __nv_bfloat16 hi = __float2bfloat16(val);
    __nv_bfloat16 lo = __float2bfloat16(val - __bfloat162float(hi));
    g_Whi[idx] = hi;
    g_Wlo[idx] = lo;
}

// zero the pad columns [400,416) of all activation planes (defensive, cheap)
__global__ void zero_pad_kernel() {
    int idx = blockIdx.x * blockDim.x + threadIdx.x;
    if (idx >= NN * 16) return;
    int row = idx >> 4;
    int c = DD + (idx & 15);
    size_t o = (size_t)row * APITCH + c;
    g_P0hi[o] = __nv_bfloat16(0.f); g_P0lo[o] = __nv_bfloat16(0.f);
    g_P1hi[o] = __nv_bfloat16(0.f); g_P1lo[o] = __nv_bfloat16(0.f);
}

// z = (1+eps)*h
__global__ void scale_init4_kernel(const float* __restrict__ h,
                                   const float* __restrict__ eps,
                                   float* __restrict__ z, int total4) {
    int i = blockIdx.x * blockDim.x + threadIdx.x;
    if (i >= total4) return;
    float s = 1.0f + eps[0];
    float4 v = ((const float4*)h)[i];
    v.x *= s; v.y *= s; v.z *= s; v.w *= s;
    ((float4*)z)[i] = v;
}

// scalar scatter (layer 1, D=79)
__global__ void scatter_add_fin_kernel(const float* __restrict__ h,
                                       const int* __restrict__ src,
                                       const int* __restrict__ dst,
                                       float* __restrict__ z, int total) {
    int idx = blockIdx.x * blockDim.x + threadIdx.x;
    if (idx >= total) return;
    int e = idx / FIN;
    int f = idx - e * FIN;
    float val = h[(size_t)src[e] * FIN + f];
    atomicAdd(&z[(size_t)dst[e] * FIN + f], val);
}

// vector-gather scatter (D=400)
__global__ void scatter_add4_kernel(const float* __restrict__ h,
                                    const int* __restrict__ src,
                                    const int* __restrict__ dst,
                                    float* __restrict__ z) {
    int idx = blockIdx.x * blockDim.x + threadIdx.x;
    if (idx >= EE * (DD / 4)) return;
    int e = idx / (DD / 4);
    int q = idx - e * (DD / 4);
    const float4 v = *(const float4*)(h + (size_t)src[e] * DD + q * 4);
    float* p = z + (size_t)dst[e] * DD + q * 4;
    atomicAdd(p + 0, v.x);
    atomicAdd(p + 1, v.y);
    atomicAdd(p + 2, v.z);
    atomicAdd(p + 3, v.w);
}

// fp32 [NN][K] -> bf16 hi/lo planes [NN][APITCH] (zero padded)
__global__ void convert_kernel(const float* __restrict__ z, int K,
                               __nv_bfloat16* __restrict__ phi,
                               __nv_bfloat16* __restrict__ plo) {
    int idx = blockIdx.x * blockDim.x + threadIdx.x;
    if (idx >= NN * (APITCH / 4)) return;
    int row = idx / (APITCH / 4);
    int q   = idx - row * (APITCH / 4);
    float v[4];
#pragma unroll
    for (int j = 0; j < 4; j++) {
        int k = q * 4 + j;
        v[j] = (k < K) ? z[(size_t)row * K + k] : 0.0f;
    }
    uint32_t h0 = pack_bf16x2(v[0], v[1]);
    uint32_t h1 = pack_bf16x2(v[2], v[3]);
    float r[4];
#pragma unroll
    for (int j = 0; j < 4; j++) {
        __nv_bfloat16 hh = __float2bfloat16(v[j]);
        r[j] = v[j] - __bfloat162float(hh);
    }
    uint32_t l0 = pack_bf16x2(r[0], r[1]);
    uint32_t l1 = pack_bf16x2(r[2], r[3]);
    size_t o = (size_t)row * APITCH + q * 4;
    *(uint2*)(phi + o) = make_uint2(h0, h1);
    *(uint2*)(plo + o) = make_uint2(l0, l1);
}

// ================= HMMA GEMM (bf16 hi/lo split, fp32 accum) =================
// C[n x 400] = act( alpha .* (A @ W) + beta )
// A as bf16 planes [n][APITCH]; W as staged planes [400][WPITCH].
// MODE 0: relu -> bf16 planes out. MODE 1: tanh -> fp32 out.
#define BM 128
#define BN 200
#define GTHREADS 640
#define SA_BYTES 10240   // 128 rows * 80B
#define SB_BYTES 16000   // 200 rows * 80B
#define ST_AHI 0
#define ST_ALO SA_BYTES
#define ST_BHI (2 * SA_BYTES)
#define ST_BLO (2 * SA_BYTES + SB_BYTES)
#define STAGE_BYTES (2 * SA_BYTES + 2 * SB_BYTES)   // 52480
#define GSMEM (2 * STAGE_BYTES)                      // 104960

__device__ __forceinline__ void load_stage(
    char* smem, uint32_t sbase,
    const __nv_bfloat16* __restrict__ Ahi, const __nv_bfloat16* __restrict__ Alo,
    const __nv_bfloat16* __restrict__ Bhi, const __nv_bfloat16* __restrict__ Blo,
    int m0, int n0, int kb, int tid) {
    int k0 = kb * 32;
#pragma unroll 1
    for (int id = tid; id < 1312; id += GTHREADS) {
        if (id < 512) {
            int row = id >> 2, ch = id & 3;
            int gr = m0 + row;
            bool valid = gr < NN;
            size_t goff = valid ? ((size_t)gr * APITCH + k0 + ch * 8) : 0;
            uint32_t sa = sbase + ST_AHI + row * 80 + ch * 16;
            cp16(sa, Ahi + goff, valid);
            cp16(sa + (ST_ALO - ST_AHI), Alo + goff, valid);
        } else {
            int id2 = id - 512;
            int row = id2 >> 2, ch = id2 & 3;
            size_t goff = (size_t)(n0 + row) * WPITCH + k0 + ch * 8;
            uint32_t sa = sbase + ST_BHI + row * 80 + ch * 16;
            cp16(sa, Bhi + goff, true);
            cp16(sa + (ST_BLO - ST_BHI), Blo + goff, true);
        }
    }
}

template <int MODE>
__global__ __launch_bounds__(GTHREADS, 1) void gemm_hmma_kernel(
    const __nv_bfloat16* __restrict__ Ahi, const __nv_bfloat16* __restrict__ Alo,
    const __nv_bfloat16* __restrict__ Whi, const __nv_bfloat16* __restrict__ Wlo,
    const float* __restrict__ alpha, const float* __restrict__ beta,
    float* __restrict__ Cf,
    __nv_bfloat16* __restrict__ Ohi, __nv_bfloat16* __restrict__ Olo,
    int kblks) {
    extern __shared__ char smem[];
    uint32_t sb = smem_to_u32(smem);
    int tid  = threadIdx.x;
    int wid  = tid >> 5;
    int lane = tid & 31;
    int wm = wid / 5;            // 0..3
    int wn = wid - wm * 5;       // 0..4
    int m0 = blockIdx.x * BM;
    int n0 = blockIdx.y * BN;

    float acc[2][5][4];
#pragma unroll
    for (int i = 0; i < 2; i++)
#pragma unroll
        for (int j = 0; j < 5; j++)
#pragma unroll
            for (int k = 0; k < 4; k++) acc[i][j][k] = 0.0f;

    load_stage(smem, sb, Ahi, Alo, Whi, Wlo, m0, n0, 0, tid);
    CP_COMMIT();

#pragma unroll 1
    for (int kb = 0; kb < kblks; kb++) {
        if (kb + 1 < kblks) {
            load_stage(smem, sb + ((kb + 1) & 1) * STAGE_BYTES,
                       Ahi, Alo, Whi, Wlo, m0, n0, kb + 1, tid);
            CP_COMMIT();
            CP_WAIT(1);
        } else {
            CP_WAIT(0);
        }
        __syncthreads();

        uint32_t sbase = sb + (kb & 1) * STAGE_BYTES;
#pragma unroll
        for (int kk = 0; kk < 2; kk++) {
            uint32_t af[2][2][4];   // [plane][mtile][4]
#pragma unroll
            for (int mt = 0; mt < 2; mt++) {
                uint32_t row  = wm * 32 + mt * 16 + (lane & 15);
                uint32_t addr = sbase + ST_AHI + row * 80 + kk * 32 + ((lane >> 4) << 4);
                LDSM4(af[0][mt], addr);
                LDSM4(af[1][mt], addr + SA_BYTES);
            }
            uint32_t bfr[2][5][2];  // [plane][ntile][2]
#pragma unroll
            for (int nt = 0; nt < 5; nt++) {
                uint32_t row  = wn * 40 + nt * 8 + (lane & 7);
                uint32_t addr = sbase + ST_BHI + row * 80 + kk * 32 + (((lane >> 3) & 1) << 4);
                LDSM2(bfr[0][nt], addr);
                LDSM2(bfr[1][nt], addr + SB_BYTES);
            }
#pragma unroll
            for (int mt = 0; mt < 2; mt++)
#pragma unroll
                for (int nt = 0; nt < 5; nt++) {
                    mma_bf16(acc[mt][nt], af[0][mt], bfr[0][nt]);  // Ahi*Bhi
                    mma_bf16(acc[mt][nt], af[1][mt], bfr[0][nt]);  // Alo*Bhi
                    mma_bf16(acc[mt][nt], af[0][mt], bfr[1][nt]);  // Ahi*Blo
                }
        }
        __syncthreads();
    }

    // ---------------- epilogue ----------------
#pragma unroll
    for (int mt = 0; mt < 2; mt++) {
#pragma unroll
        for (int nt = 0; nt < 5; nt++) {
            int c  = n0 + wn * 40 + nt * 8 + (lane & 3) * 2;
            int r0 = m0 + wm * 32 + mt * 16 + (lane >> 2);
            float a0 = alpha ? alpha[c]     : 1.0f;
            float a1 = alpha ? alpha[c + 1] : 1.0f;
            float b0 = beta[c], b1 = beta[c + 1];
            float v00 = acc[mt][nt][0] * a0 + b0;
            float v01 = acc[mt][nt][1] * a1 + b1;
            float v10 = acc[mt][nt][2] * a0 + b0;
            float v11 = acc[mt][nt][3] * a1 + b1;
            if (MODE == 0) {
                v00 = fmaxf(v00, 0.f); v01 = fmaxf(v01, 0.f);
                v10 = fmaxf(v10, 0.f); v11 = fmaxf(v11, 0.f);
                if (r0 < NN) {
                    uint32_t hp = pack_bf16x2(v00, v01);
                    __nv_bfloat16 h0 = __float2bfloat16(v00);
                    __nv_bfloat16 h1 = __float2bfloat16(v01);
                    uint32_t lp = pack_bf16x2(v00 - __bfloat162float(h0),
                                              v01 - __bfloat162float(h1));
                    ((uint32_t*)Ohi)[(size_t)r0 * AP_U32 + (c >> 1)] = hp;
                    ((uint32_t*)Olo)[(size_t)r0 * AP_U32 + (c >> 1)] = lp;
                }
                if (r0 + 8 < NN) {
                    uint32_t hp = pack_bf16x2(v10, v11);
                    __nv_bfloat16 h0 = __float2bfloat16(v10);
                    __nv_bfloat16 h1 = __float2bfloat16(v11);
                    uint32_t lp = pack_bf16x2(v10 - __bfloat162float(h0),
                                              v11 - __bfloat162float(h1));
                    ((uint32_t*)Ohi)[(size_t)(r0 + 8) * AP_U32 + (c >> 1)] = hp;
                    ((uint32_t*)Olo)[(size_t)(r0 + 8) * AP_U32 + (c >> 1)] = lp;
                }
            } else {
                if (r0 < NN) {
                    float2 o = make_float2(tanhf(v00), tanhf(v01));
                    *(float2*)(Cf + (size_t)r0 * DD + c) = o;
                }
                if (r0 + 8 < NN) {
                    float2 o = make_float2(tanhf(v10), tanhf(v11));
                    *(float2*)(Cf + (size_t)(r0 + 8) * DD + c) = o;
                }
            }
        }
    }
}

// ================= pooling + final projection (atomic-free) =================

__device__ __forceinline__ int lower_bound_batch(const int* __restrict__ b, int val) {
    int lo = 0, hi = NN;
    while (lo < hi) {
        int mid = (lo + hi) >> 1;
        if (b[mid] < val) lo = mid + 1; else hi = mid;
    }
    return lo;
}

__global__ __launch_bounds__(256) void pool_out_kernel(
    const float* __restrict__ h, const int* __restrict__ batch,
    const float* __restrict__ w, const float* __restrict__ b,
    float* __restrict__ out) {
    int g   = blockIdx.x;
    int tid = threadIdx.x;
    int lo = lower_bound_batch(batch, g);
    int hi = lower_bound_batch(batch, g + 1);
    float invc = 1.0f / fmaxf((float)(hi - lo), 1.0f);
    float part = 0.0f;
    for (int f = tid; f < DD; f += 256) {
        float mx = -INFINITY, sm = 0.0f;
        for (int node = lo; node < hi; node++) {
            float v = h[(size_t)node * DD + f];
            mx = fmaxf(mx, v);
            sm += v;
        }
        if (hi == lo) mx = 0.0f;
        part += mx * w[f] + sm * invc * w[DD + f];
    }
#pragma unroll
    for (int o = 16; o > 0; o >>= 1) part += __shfl_down_sync(0xffffffffu, part, o);
    __shared__ float sh[8];
    if ((tid & 31) == 0) sh[tid >> 5] = part;
    __syncthreads();
    if (tid == 0) {
        float t = 0.0f;
#pragma unroll
        for (int i = 0; i < 8; i++) t += sh[i];
        out[g] = t + b[0];
    }
}

// ================= host orchestration =================

static inline int ceil_div(int a, int b) { return (a + b - 1) / b; }

extern "C" void kernel_launch(void* const* d_in, const int* in_sizes, int n_in,
                              void* d_out, int out_size) {
    const float* x     = (const float*)d_in[0];
    const int*   ei    = (const int*)d_in[1];
    const int*   src   = ei;
    const int*   dst   = ei + EE;
    const int*   batch = (const int*)d_in[2];
    int base = (in_sizes[3] == 1) ? 4 : 3;

    const float* mlp1_w1   = (const float*)d_in[base + 0];
    const float* mlp1_b1   = (const float*)d_in[base + 1];
    const float* mlp1_bn_g = (const float*)d_in[base + 2];
    const float* mlp1_bn_b = (const float*)d_in[base + 3];
    const float* mlp1_bn_m = (const float*)d_in[base + 4];
    const float* mlp1_bn_v = (const float*)d_in[base + 5];
    const float* mlp1_w2   = (const float*)d_in[base + 6];
    const float* mlp1_b2   = (const float*)d_in[base + 7];
    const float* mlp2_w1   = (const float*)d_in[base + 8];
    const float* mlp2_b1   = (const float*)d_in[base + 9];
    const float* mlp2_bn_g = (const float*)d_in[base + 10];
    const float* mlp2_bn_b = (const float*)d_in[base + 11];
    const float* mlp2_bn_m = (const float*)d_in[base + 12];
    const float* mlp2_bn_v = (const float*)d_in[base + 13];
    const float* mlp2_w2   = (const float*)d_in[base + 14];
    const float* mlp2_b2   = (const float*)d_in[base + 15];
    const float* out1_w    = (const float*)d_in[base + 16];
    const float* out1_b    = (const float*)d_in[base + 17];
    const float* out2_w    = (const float*)d_in[base + 18];
    const float* out2_b    = (const float*)d_in[base + 19];
    const float* out3_w    = (const float*)d_in[base + 20];
    const float* out3_b    = (const float*)d_in[base + 21];
    const float* out_w     = (const float*)d_in[base + 22];
    const float* out_b     = (const float*)d_in[base + 23];
    const float* eps1      = (const float*)d_in[base + 24];
    const float* eps2      = (const float*)d_in[base + 25];
    const float* eps3      = (const float*)d_in[base + 26];

    float* out = (float*)d_out;

    float *bufA, *bufB, *alpha1, *beta1, *alpha2, *beta2;
    __nv_bfloat16 *whi, *wlo, *p0h, *p0l, *p1h, *p1l;
    cudaGetSymbolAddress((void**)&bufA, g_bufA);
    cudaGetSymbolAddress((void**)&bufB, g_bufB);
    cudaGetSymbolAddress((void**)&alpha1, g_alpha1);
    cudaGetSymbolAddress((void**)&beta1,  g_beta1);
    cudaGetSymbolAddress((void**)&alpha2, g_alpha2);
    cudaGetSymbolAddress((void**)&beta2,  g_beta2);
    cudaGetSymbolAddress((void**)&whi, g_Whi);
    cudaGetSymbolAddress((void**)&wlo, g_Wlo);
    cudaGetSymbolAddress((void**)&p0h, g_P0hi);
    cudaGetSymbolAddress((void**)&p0l, g_P0lo);
    cudaGetSymbolAddress((void**)&p1h, g_P1hi);
    cudaGetSymbolAddress((void**)&p1l, g_P1lo);

    cudaFuncSetAttribute(gemm_hmma_kernel<0>,
                         cudaFuncAttributeMaxDynamicSharedMemorySize, GSMEM);
    cudaFuncSetAttribute(gemm_hmma_kernel<1>,
                         cudaFuncAttributeMaxDynamicSharedMemorySize, GSMEM);

    // ---- staging (idempotent, cheap) ----
    {
        int tot = NMATS * DD * WPITCH;
        stage_w_kernel<<<ceil_div(tot, 256), 256>>>(mlp1_w1, mlp1_w2, mlp2_w1,
                                                    mlp2_w2, out1_w, out2_w, out3_w);
        make_ab_kernel<<<ceil_div(DD, 128), 128>>>(mlp1_b1, mlp1_bn_g, mlp1_bn_b,
                                                   mlp1_bn_m, mlp1_bn_v, alpha1, beta1);
        make_ab_kernel<<<ceil_div(DD, 128), 128>>>(mlp2_b1, mlp2_bn_g, mlp2_bn_b,
                                                   mlp2_bn_m, mlp2_bn_v, alpha2, beta2);
        zero_pad_kernel<<<ceil_div(NN * 16, 256), 256>>>();
    }

    dim3 ggrid(ceil_div(NN, BM), 2);   // (391, 2)
    size_t wmat = (size_t)DD * WPITCH;
    int cv_tot = NN * (APITCH / 4);

    // ---------- layer 1 ----------
    {
        int tot4 = NN * FIN / 4;
        scale_init4_kernel<<<ceil_div(tot4, 256), 256>>>(x, eps1, bufA, tot4);
        int etot = EE * FIN;
        scatter_add_fin_kernel<<<ceil_div(etot, 256), 256>>>(x, src, dst, bufA, etot);
        convert_kernel<<<ceil_div(cv_tot, 256), 256>>>(bufA, FIN, p0h, p0l);
        gemm_hmma_kernel<0><<<ggrid, GTHREADS, GSMEM>>>(p0h, p0l, whi + 0 * wmat, wlo + 0 * wmat,
                                                        alpha1, beta1, nullptr, p1h, p1l, 3);
        gemm_hmma_kernel<0><<<ggrid, GTHREADS, GSMEM>>>(p1h, p1l, whi + 1 * wmat, wlo + 1 * wmat,
                                                        nullptr, mlp1_b2, nullptr, p0h, p0l, 13);
        gemm_hmma_kernel<1><<<ggrid, GTHREADS, GSMEM>>>(p0h, p0l, whi + 4 * wmat, wlo + 4 * wmat,
                                                        nullptr, out1_b, bufB, nullptr, nullptr, 13);
    }
    // ---------- layer 2 ----------
    {
        int tot4 = NN * DD / 4;
        scale_init4_kernel<<<ceil_div(tot4, 256), 256>>>(bufB, eps2, bufA, tot4);
        int etot4 = EE * (DD / 4);
        scatter_add4_kernel<<<ceil_div(etot4, 256), 256>>>(bufB, src, dst, bufA);
        convert_kernel<<<ceil_div(cv_tot, 256), 256>>>(bufA, DD, p0h, p0l);
        gemm_hmma_kernel<0><<<ggrid, GTHREADS, GSMEM>>>(p0h, p0l, whi + 2 * wmat, wlo + 2 * wmat,
                                                        alpha2, beta2, nullptr, p1h, p1l, 13);
        gemm_hmma_kernel<0><<<ggrid, GTHREADS, GSMEM>>>(p1h, p1l, whi + 3 * wmat, wlo + 3 * wmat,
                                                        nullptr, mlp2_b2, nullptr, p0h, p0l, 13);
        gemm_hmma_kernel<1><<<ggrid, GTHREADS, GSMEM>>>(p0h, p0l, whi + 5 * wmat, wlo + 5 * wmat,
                                                        nullptr, out2_b, bufB, nullptr, nullptr, 13);
    }
    // ---------- layer 3 ----------
    {
        int tot4 = NN * DD / 4;
        scale_init4_kernel<<<ceil_div(tot4, 256), 256>>>(bufB, eps3, bufA, tot4);
        int etot4 = EE * (DD / 4);
        scatter_add4_kernel<<<ceil_div(etot4, 256), 256>>>(bufB, src, dst, bufA);
        convert_kernel<<<ceil_div(cv_tot, 256), 256>>>(bufA, DD, p0h, p0l);
        gemm_hmma_kernel<0><<<ggrid, GTHREADS, GSMEM>>>(p0h, p0l, whi + 2 * wmat, wlo + 2 * wmat,
                                                        alpha2, beta2, nullptr, p1h, p1l, 13);
        gemm_hmma_kernel<0><<<ggrid, GTHREADS, GSMEM>>>(p1h, p1l, whi + 3 * wmat, wlo + 3 * wmat,
                                                        nullptr, mlp2_b2, nullptr, p0h, p0l, 13);
        gemm_hmma_kernel<1><<<ggrid, GTHREADS, GSMEM>>>(p0h, p0l, whi + 6 * wmat, wlo + 6 * wmat,
                                                        nullptr, out3_b, bufB, nullptr, nullptr, 13);
    }
    // ---------- pooling + output ----------
    pool_out_kernel<<<GG, 256>>>(bufB, batch, out_w, out_b, out);
    (void)n_in; (void)out_size;
}

// round 4
// speedup vs baseline: 2.5441x; 1.1974x over previous
#include <cuda_runtime.h>
#include <cuda_bf16.h>
#include <cstdint>
#include <math.h>

// ================= problem constants =================
#define NN    50000
#define EE    400000
#define GG    256
#define FIN   79
#define DD    400
#define BN_EPS 1e-5f

#define NMATS  7
#define WPITCH 416            // padded K pitch for staged weights (13 * 32)
#define APITCH 416            // padded K pitch for activation planes
#define AP_U32 (APITCH / 2)   // 208 u32 per row
#define XP     80             // padded layer-1 feature pitch

// ================= scratch (device globals; zero-initialized) ============
__device__ float g_bufA[(size_t)NN * DD];
__device__ float g_bufB[(size_t)NN * DD];
__device__ __align__(16) __nv_bfloat16 g_P0hi[(size_t)NN * APITCH];
__device__ __align__(16) __nv_bfloat16 g_P0lo[(size_t)NN * APITCH];
__device__ __align__(16) __nv_bfloat16 g_P1hi[(size_t)NN * APITCH];
__device__ __align__(16) __nv_bfloat16 g_P1lo[(size_t)NN * APITCH];
__device__ __align__(16) __nv_bfloat16 g_Whi[(size_t)NMATS * DD * WPITCH];
__device__ __align__(16) __nv_bfloat16 g_Wlo[(size_t)NMATS * DD * WPITCH];
__device__ float g_alpha1[DD], g_beta1[DD], g_alpha2[DD], g_beta2[DD];

// ================= helpers =================
__device__ __forceinline__ uint32_t smem_to_u32(const void* p) {
    uint32_t a;
    asm("{ .reg .u64 t; cvta.to.shared.u64 t, %1; cvt.u32.u64 %0, t; }"
        : "=r"(a) : "l"(p));
    return a;
}

__device__ __forceinline__ void cp16(uint32_t saddr, const void* gptr, bool valid) {
    int sz = valid ? 16 : 0;
    asm volatile("cp.async.cg.shared.global [%0], [%1], 16, %2;"
                 :: "r"(saddr), "l"(gptr), "r"(sz));
}
#define CP_COMMIT() asm volatile("cp.async.commit_group;")
#define CP_WAIT(n)  asm volatile("cp.async.wait_group %0;" :: "n"(n))

#define LDSM4(R, addr) \
    asm volatile("ldmatrix.sync.aligned.m8n8.x4.shared.b16 {%0,%1,%2,%3}, [%4];" \
        : "=r"((R)[0]), "=r"((R)[1]), "=r"((R)[2]), "=r"((R)[3]) : "r"(addr))

#define LDSM2(R, addr) \
    asm volatile("ldmatrix.sync.aligned.m8n8.x2.shared.b16 {%0,%1}, [%2];" \
        : "=r"((R)[0]), "=r"((R)[1]) : "r"(addr))

__device__ __forceinline__ void mma_bf16(float* d, const uint32_t* a, const uint32_t* b) {
    asm volatile(
        "mma.sync.aligned.m16n8k16.row.col.f32.bf16.bf16.f32 "
        "{%0,%1,%2,%3}, {%4,%5,%6,%7}, {%8,%9}, {%0,%1,%2,%3};"
        : "+f"(d[0]), "+f"(d[1]), "+f"(d[2]), "+f"(d[3])
        : "r"(a[0]), "r"(a[1]), "r"(a[2]), "r"(a[3]), "r"(b[0]), "r"(b[1]));
}

__device__ __forceinline__ uint32_t pack_bf16x2(float x, float y) {
    __nv_bfloat16 hx = __float2bfloat16(x);
    __nv_bfloat16 hy = __float2bfloat16(y);
    return ((uint32_t)*(uint16_t*)&hy << 16) | *(uint16_t*)&hx;
}

__device__ __forceinline__ void red_add_v4(float* p, float4 v) {
    asm volatile("red.global.add.v4.f32 [%0], {%1, %2, %3, %4};"
                 :: "l"(p), "f"(v.x), "f"(v.y), "f"(v.z), "f"(v.w) : "memory");
}

// ================= small kernels =================

__global__ void make_ab_kernel(const float* __restrict__ b1,
                               const float* __restrict__ g,
                               const float* __restrict__ bb,
                               const float* __restrict__ m,
                               const float* __restrict__ v,
                               float* __restrict__ alpha,
                               float* __restrict__ beta) {
    int c = blockIdx.x * blockDim.x + threadIdx.x;
    if (c >= DD) return;
    float a = g[c] * rsqrtf(v[c] + BN_EPS);
    alpha[c] = a;
    beta[c]  = (b1[c] - m[c]) * a + bb[c];
}

// Stage W^T as bf16 hi/lo planes: layout [mat][n=400][k padded to 416]
__global__ void stage_w_kernel(const float* __restrict__ w0, const float* __restrict__ w1,
                               const float* __restrict__ w2, const float* __restrict__ w3,
                               const float* __restrict__ w4, const float* __restrict__ w5,
                               const float* __restrict__ w6) {
    int idx = blockIdx.x * blockDim.x + threadIdx.x;
    const int per_mat = DD * WPITCH;
    if (idx >= NMATS * per_mat) return;
    int m = idx / per_mat;
    int r = idx - m * per_mat;
    int n = r / WPITCH;
    int k = r - n * WPITCH;
    int Km = (m == 0) ? FIN : DD;
    const float* W;
    switch (m) {
        case 0: W = w0; break; case 1: W = w1; break; case 2: W = w2; break;
        case 3: W = w3; break; case 4: W = w4; break; case 5: W = w5; break;
        default: W = w6; break;
    }
    float val = (k < Km) ? W[(size_t)k * DD + n] : 0.0f;
    __nv_bfloat16 hi = __float2bfloat16(val);
    __nv_bfloat16 lo = __float2bfloat16(val - __bfloat162float(hi));
    g_Whi[idx] = hi;
    g_Wlo[idx] = lo;
}

// zero the pad columns [400,416) of all activation planes
__global__ void zero_pad_kernel() {
    int idx = blockIdx.x * blockDim.x + threadIdx.x;
    if (idx >= NN * 16) return;
    int row = idx >> 4;
    int c = DD + (idx & 15);
    size_t o = (size_t)row * APITCH + c;
    g_P0hi[o] = __nv_bfloat16(0.f); g_P0lo[o] = __nv_bfloat16(0.f);
    g_P1hi[o] = __nv_bfloat16(0.f); g_P1lo[o] = __nv_bfloat16(0.f);
}

// layer-1: pad x into [NN][80] (col 79 = 0) and write z-init = (1+eps)*x
__global__ void pad_scale_kernel(const float* __restrict__ x,
                                 const float* __restrict__ eps,
                                 float* __restrict__ xpad,
                                 float* __restrict__ z) {
    int idx = blockIdx.x * blockDim.x + threadIdx.x;
    if (idx >= NN * XP) return;
    int row = idx / XP;
    int col = idx - row * XP;
    float v = (col < FIN) ? x[(size_t)row * FIN + col] : 0.0f;
    float s = 1.0f + eps[0];
    xpad[idx] = v;
    z[idx]    = s * v;
}

// layer-1 scatter: v4 red over 20 quarters of the 80-col padded plane
__global__ void scatter_add_x_kernel(const float* __restrict__ xpad,
                                     const int* __restrict__ src,
                                     const int* __restrict__ dst,
                                     float* __restrict__ z) {
    int idx = blockIdx.x * blockDim.x + threadIdx.x;
    if (idx >= EE * (XP / 4)) return;
    int e = idx / (XP / 4);
    int q = idx - e * (XP / 4);
    const float4 v = *(const float4*)(xpad + (size_t)src[e] * XP + q * 4);
    red_add_v4((float*)(z + (size_t)dst[e] * XP + q * 4), v);
}

// vector-gather scatter (D=400), v4 red atomics
__global__ void scatter_add4_kernel(const float* __restrict__ h,
                                    const int* __restrict__ src,
                                    const int* __restrict__ dst,
                                    float* __restrict__ z) {
    int idx = blockIdx.x * blockDim.x + threadIdx.x;
    if (idx >= EE * (DD / 4)) return;
    int e = idx / (DD / 4);
    int q = idx - e * (DD / 4);
    const float4 v = *(const float4*)(h + (size_t)src[e] * DD + q * 4);
    red_add_v4((float*)(z + (size_t)dst[e] * DD + q * 4), v);
}

// fp32 [NN][Kp] -> bf16 hi/lo planes [NN][APITCH] (zero padded beyond Kp)
__global__ void convert_kernel(const float* __restrict__ z, int Kp,
                               __nv_bfloat16* __restrict__ phi,
                               __nv_bfloat16* __restrict__ plo) {
    int idx = blockIdx.x * blockDim.x + threadIdx.x;
    if (idx >= NN * (APITCH / 4)) return;
    int row = idx / (APITCH / 4);
    int q   = idx - row * (APITCH / 4);
    float v[4];
#pragma unroll
    for (int j = 0; j < 4; j++) {
        int k = q * 4 + j;
        v[j] = (k < Kp) ? z[(size_t)row * Kp + k] : 0.0f;
    }
    uint32_t h0 = pack_bf16x2(v[0], v[1]);
    uint32_t h1 = pack_bf16x2(v[2], v[3]);
    float r[4];
#pragma unroll
    for (int j = 0; j < 4; j++) {
        __nv_bfloat16 hh = __float2bfloat16(v[j]);
        r[j] = v[j] - __bfloat162float(hh);
    }
    uint32_t l0 = pack_bf16x2(r[0], r[1]);
    uint32_t l1 = pack_bf16x2(r[2], r[3]);
    size_t o = (size_t)row * APITCH + q * 4;
    *(uint2*)(phi + o) = make_uint2(h0, h1);
    *(uint2*)(plo + o) = make_uint2(l0, l1);
}

// ================= HMMA GEMM (bf16 hi/lo split, fp32 accum) =================
// MODE 0: relu -> bf16 planes out.
// MODE 1: tanh -> fp32 out; optionally also writes (1+eps)*tanh into Zinit.
#define BM 128
#define BN 200
#define GTHREADS 640
#define SA_BYTES 10240   // 128 rows * 80B
#define SB_BYTES 16000   // 200 rows * 80B
#define ST_AHI 0
#define ST_ALO SA_BYTES
#define ST_BHI (2 * SA_BYTES)
#define ST_BLO (2 * SA_BYTES + SB_BYTES)
#define STAGE_BYTES (2 * SA_BYTES + 2 * SB_BYTES)   // 52480
#define GSMEM (2 * STAGE_BYTES)                      // 104960

__device__ __forceinline__ void load_stage(
    char* smem, uint32_t sbase,
    const __nv_bfloat16* __restrict__ Ahi, const __nv_bfloat16* __restrict__ Alo,
    const __nv_bfloat16* __restrict__ Bhi, const __nv_bfloat16* __restrict__ Blo,
    int m0, int n0, int kb, int tid) {
    int k0 = kb * 32;
#pragma unroll 1
    for (int id = tid; id < 1312; id += GTHREADS) {
        if (id < 512) {
            int row = id >> 2, ch = id & 3;
            int gr = m0 + row;
            bool valid = gr < NN;
            size_t goff = valid ? ((size_t)gr * APITCH + k0 + ch * 8) : 0;
            uint32_t sa = sbase + ST_AHI + row * 80 + ch * 16;
            cp16(sa, Ahi + goff, valid);
            cp16(sa + (ST_ALO - ST_AHI), Alo + goff, valid);
        } else {
            int id2 = id - 512;
            int row = id2 >> 2, ch = id2 & 3;
            size_t goff = (size_t)(n0 + row) * WPITCH + k0 + ch * 8;
            uint32_t sa = sbase + ST_BHI + row * 80 + ch * 16;
            cp16(sa, Bhi + goff, true);
            cp16(sa + (ST_BLO - ST_BHI), Blo + goff, true);
        }
    }
}

template <int MODE>
__global__ __launch_bounds__(GTHREADS, 1) void gemm_hmma_kernel(
    const __nv_bfloat16* __restrict__ Ahi, const __nv_bfloat16* __restrict__ Alo,
    const __nv_bfloat16* __restrict__ Whi, const __nv_bfloat16* __restrict__ Wlo,
    const float* __restrict__ alpha, const float* __restrict__ beta,
    float* __restrict__ Cf,
    __nv_bfloat16* __restrict__ Ohi, __nv_bfloat16* __restrict__ Olo,
    const float* __restrict__ epsn, float* __restrict__ Zinit,
    int kblks) {
    extern __shared__ char smem[];
    uint32_t sb = smem_to_u32(smem);
    int tid  = threadIdx.x;
    int wid  = tid >> 5;
    int lane = tid & 31;
    int wm = wid / 5;            // 0..3
    int wn = wid - wm * 5;       // 0..4
    int m0 = blockIdx.x * BM;
    int n0 = blockIdx.y * BN;

    float acc[2][5][4];
#pragma unroll
    for (int i = 0; i < 2; i++)
#pragma unroll
        for (int j = 0; j < 5; j++)
#pragma unroll
            for (int k = 0; k < 4; k++) acc[i][j][k] = 0.0f;

    load_stage(smem, sb, Ahi, Alo, Whi, Wlo, m0, n0, 0, tid);
    CP_COMMIT();

#pragma unroll 1
    for (int kb = 0; kb < kblks; kb++) {
        if (kb + 1 < kblks) {
            load_stage(smem, sb + ((kb + 1) & 1) * STAGE_BYTES,
                       Ahi, Alo, Whi, Wlo, m0, n0, kb + 1, tid);
            CP_COMMIT();
            CP_WAIT(1);
        } else {
            CP_WAIT(0);
        }
        __syncthreads();

        uint32_t sbase = sb + (kb & 1) * STAGE_BYTES;
#pragma unroll
        for (int kk = 0; kk < 2; kk++) {
            uint32_t af[2][2][4];
#pragma unroll
            for (int mt = 0; mt < 2; mt++) {
                uint32_t row  = wm * 32 + mt * 16 + (lane & 15);
                uint32_t addr = sbase + ST_AHI + row * 80 + kk * 32 + ((lane >> 4) << 4);
                LDSM4(af[0][mt], addr);
                LDSM4(af[1][mt], addr + SA_BYTES);
            }
            uint32_t bfr[2][5][2];
#pragma unroll
            for (int nt = 0; nt < 5; nt++) {
                uint32_t row  = wn * 40 + nt * 8 + (lane & 7);
                uint32_t addr = sbase + ST_BHI + row * 80 + kk * 32 + (((lane >> 3) & 1) << 4);
                LDSM2(bfr[0][nt], addr);
                LDSM2(bfr[1][nt], addr + SB_BYTES);
            }
#pragma unroll
            for (int mt = 0; mt < 2; mt++)
#pragma unroll
                for (int nt = 0; nt < 5; nt++) {
                    mma_bf16(acc[mt][nt], af[0][mt], bfr[0][nt]);  // Ahi*Bhi
                    mma_bf16(acc[mt][nt], af[1][mt], bfr[0][nt]);  // Alo*Bhi
                    mma_bf16(acc[mt][nt], af[0][mt], bfr[1][nt]);  // Ahi*Blo
                }
        }
        __syncthreads();
    }

    // ---------------- epilogue ----------------
    float sc = (MODE == 1 && Zinit) ? (1.0f + epsn[0]) : 0.0f;
#pragma unroll
    for (int mt = 0; mt < 2; mt++) {
#pragma unroll
        for (int nt = 0; nt < 5; nt++) {
            int c  = n0 + wn * 40 + nt * 8 + (lane & 3) * 2;
            int r0 = m0 + wm * 32 + mt * 16 + (lane >> 2);
            float a0 = alpha ? alpha[c]     : 1.0f;
            float a1 = alpha ? alpha[c + 1] : 1.0f;
            float b0 = beta[c], b1 = beta[c + 1];
            float v00 = acc[mt][nt][0] * a0 + b0;
            float v01 = acc[mt][nt][1] * a1 + b1;
            float v10 = acc[mt][nt][2] * a0 + b0;
            float v11 = acc[mt][nt][3] * a1 + b1;
            if (MODE == 0) {
                v00 = fmaxf(v00, 0.f); v01 = fmaxf(v01, 0.f);
                v10 = fmaxf(v10, 0.f); v11 = fmaxf(v11, 0.f);
                if (r0 < NN) {
                    uint32_t hp = pack_bf16x2(v00, v01);
                    __nv_bfloat16 h0 = __float2bfloat16(v00);
                    __nv_bfloat16 h1 = __float2bfloat16(v01);
                    uint32_t lp = pack_bf16x2(v00 - __bfloat162float(h0),
                                              v01 - __bfloat162float(h1));
                    ((uint32_t*)Ohi)[(size_t)r0 * AP_U32 + (c >> 1)] = hp;
                    ((uint32_t*)Olo)[(size_t)r0 * AP_U32 + (c >> 1)] = lp;
                }
                if (r0 + 8 < NN) {
                    uint32_t hp = pack_bf16x2(v10, v11);
                    __nv_bfloat16 h0 = __float2bfloat16(v10);
                    __nv_bfloat16 h1 = __float2bfloat16(v11);
                    uint32_t lp = pack_bf16x2(v10 - __bfloat162float(h0),
                                              v11 - __bfloat162float(h1));
                    ((uint32_t*)Ohi)[(size_t)(r0 + 8) * AP_U32 + (c >> 1)] = hp;
                    ((uint32_t*)Olo)[(size_t)(r0 + 8) * AP_U32 + (c >> 1)] = lp;
                }
            } else {
                float t00 = tanhf(v00), t01 = tanhf(v01);
                float t10 = tanhf(v10), t11 = tanhf(v11);
                if (r0 < NN) {
                    *(float2*)(Cf + (size_t)r0 * DD + c) = make_float2(t00, t01);
                    if (Zinit)
                        *(float2*)(Zinit + (size_t)r0 * DD + c) =
                            make_float2(sc * t00, sc * t01);
                }
                if (r0 + 8 < NN) {
                    *(float2*)(Cf + (size_t)(r0 + 8) * DD + c) = make_float2(t10, t11);
                    if (Zinit)
                        *(float2*)(Zinit + (size_t)(r0 + 8) * DD + c) =
                            make_float2(sc * t10, sc * t11);
                }
            }
        }
    }
}

// ================= pooling + final projection (atomic-free) =================

__device__ __forceinline__ int lower_bound_batch(const int* __restrict__ b, int val) {
    int lo = 0, hi = NN;
    while (lo < hi) {
        int mid = (lo + hi) >> 1;
        if (b[mid] < val) lo = mid + 1; else hi = mid;
    }
    return lo;
}

__global__ __launch_bounds__(256) void pool_out_kernel(
    const float* __restrict__ h, const int* __restrict__ batch,
    const float* __restrict__ w, const float* __restrict__ b,
    float* __restrict__ out) {
    int g   = blockIdx.x;
    int tid = threadIdx.x;
    int lo = lower_bound_batch(batch, g);
    int hi = lower_bound_batch(batch, g + 1);
    float invc = 1.0f / fmaxf((float)(hi - lo), 1.0f);
    float part = 0.0f;
    for (int f = tid; f < DD; f += 256) {
        float mx = -INFINITY, sm = 0.0f;
        for (int node = lo; node < hi; node++) {
            float v = h[(size_t)node * DD + f];
            mx = fmaxf(mx, v);
            sm += v;
        }
        if (hi == lo) mx = 0.0f;
        part += mx * w[f] + sm * invc * w[DD + f];
    }
#pragma unroll
    for (int o = 16; o > 0; o >>= 1) part += __shfl_down_sync(0xffffffffu, part, o);
    __shared__ float sh[8];
    if ((tid & 31) == 0) sh[tid >> 5] = part;
    __syncthreads();
    if (tid == 0) {
        float t = 0.0f;
#pragma unroll
        for (int i = 0; i < 8; i++) t += sh[i];
        out[g] = t + b[0];
    }
}

// ================= host orchestration =================

static inline int ceil_div(int a, int b) { return (a + b - 1) / b; }

extern "C" void kernel_launch(void* const* d_in, const int* in_sizes, int n_in,
                              void* d_out, int out_size) {
    const float* x     = (const float*)d_in[0];
    const int*   ei    = (const int*)d_in[1];
    const int*   src   = ei;
    const int*   dst   = ei + EE;
    const int*   batch = (const int*)d_in[2];
    int base = (in_sizes[3] == 1) ? 4 : 3;

    const float* mlp1_w1   = (const float*)d_in[base + 0];
    const float* mlp1_b1   = (const float*)d_in[base + 1];
    const float* mlp1_bn_g = (const float*)d_in[base + 2];
    const float* mlp1_bn_b = (const float*)d_in[base + 3];
    const float* mlp1_bn_m = (const float*)d_in[base + 4];
    const float* mlp1_bn_v = (const float*)d_in[base + 5];
    const float* mlp1_w2   = (const float*)d_in[base + 6];
    const float* mlp1_b2   = (const float*)d_in[base + 7];
    const float* mlp2_w1   = (const float*)d_in[base + 8];
    const float* mlp2_b1   = (const float*)d_in[base + 9];
    const float* mlp2_bn_g = (const float*)d_in[base + 10];
    const float* mlp2_bn_b = (const float*)d_in[base + 11];
    const float* mlp2_bn_m = (const float*)d_in[base + 12];
    const float* mlp2_bn_v = (const float*)d_in[base + 13];
    const float* mlp2_w2   = (const float*)d_in[base + 14];
    const float* mlp2_b2   = (const float*)d_in[base + 15];
    const float* out1_w    = (const float*)d_in[base + 16];
    const float* out1_b    = (const float*)d_in[base + 17];
    const float* out2_w    = (const float*)d_in[base + 18];
    const float* out2_b    = (const float*)d_in[base + 19];
    const float* out3_w    = (const float*)d_in[base + 20];
    const float* out3_b    = (const float*)d_in[base + 21];
    const float* out_w     = (const float*)d_in[base + 22];
    const float* out_b     = (const float*)d_in[base + 23];
    const float* eps1      = (const float*)d_in[base + 24];
    const float* eps2      = (const float*)d_in[base + 25];
    const float* eps3      = (const float*)d_in[base + 26];

    float* out = (float*)d_out;

    float *bufA, *bufB, *alpha1, *beta1, *alpha2, *beta2;
    __nv_bfloat16 *whi, *wlo, *p0h, *p0l, *p1h, *p1l;
    cudaGetSymbolAddress((void**)&bufA, g_bufA);
    cudaGetSymbolAddress((void**)&bufB, g_bufB);
    cudaGetSymbolAddress((void**)&alpha1, g_alpha1);
    cudaGetSymbolAddress((void**)&beta1,  g_beta1);
    cudaGetSymbolAddress((void**)&alpha2, g_alpha2);
    cudaGetSymbolAddress((void**)&beta2,  g_beta2);
    cudaGetSymbolAddress((void**)&whi, g_Whi);
    cudaGetSymbolAddress((void**)&wlo, g_Wlo);
    cudaGetSymbolAddress((void**)&p0h, g_P0hi);
    cudaGetSymbolAddress((void**)&p0l, g_P0lo);
    cudaGetSymbolAddress((void**)&p1h, g_P1hi);
    cudaGetSymbolAddress((void**)&p1l, g_P1lo);

    cudaFuncSetAttribute(gemm_hmma_kernel<0>,
                         cudaFuncAttributeMaxDynamicSharedMemorySize, GSMEM);
    cudaFuncSetAttribute(gemm_hmma_kernel<1>,
                         cudaFuncAttributeMaxDynamicSharedMemorySize, GSMEM);

    // ---- staging ----
    {
        int tot = NMATS * DD * WPITCH;
        stage_w_kernel<<<ceil_div(tot, 256), 256>>>(mlp1_w1, mlp1_w2, mlp2_w1,
                                                    mlp2_w2, out1_w, out2_w, out3_w);
        make_ab_kernel<<<ceil_div(DD, 128), 128>>>(mlp1_b1, mlp1_bn_g, mlp1_bn_b,
                                                   mlp1_bn_m, mlp1_bn_v, alpha1, beta1);
        make_ab_kernel<<<ceil_div(DD, 128), 128>>>(mlp2_b1, mlp2_bn_g, mlp2_bn_b,
                                                   mlp2_bn_m, mlp2_bn_v, alpha2, beta2);
        zero_pad_kernel<<<ceil_div(NN * 16, 256), 256>>>();
    }

    dim3 ggrid(ceil_div(NN, BM), 2);   // (391, 2)
    size_t wmat = (size_t)DD * WPITCH;
    int cv_tot = NN * (APITCH / 4);

    // ---------- layer 1 ----------
    {
        // bufB[0 : NN*80) used as padded x; bufA[0 : NN*80) as z
        pad_scale_kernel<<<ceil_div(NN * XP, 256), 256>>>(x, eps1, bufB, bufA);
        int et = EE * (XP / 4);
        scatter_add_x_kernel<<<ceil_div(et, 256), 256>>>(bufB, src, dst, bufA);
        convert_kernel<<<ceil_div(cv_tot, 256), 256>>>(bufA, XP, p0h, p0l);
        gemm_hmma_kernel<0><<<ggrid, GTHREADS, GSMEM>>>(p0h, p0l, whi + 0 * wmat, wlo + 0 * wmat,
                                                        alpha1, beta1, nullptr, p1h, p1l,
                                                        nullptr, nullptr, 3);
        gemm_hmma_kernel<0><<<ggrid, GTHREADS, GSMEM>>>(p1h, p1l, whi + 1 * wmat, wlo + 1 * wmat,
                                                        nullptr, mlp1_b2, nullptr, p0h, p0l,
                                                        nullptr, nullptr, 13);
        // tanh out -> bufB (h), plus (1+eps2)*h -> bufA (next layer's z init)
        gemm_hmma_kernel<1><<<ggrid, GTHREADS, GSMEM>>>(p0h, p0l, whi + 4 * wmat, wlo + 4 * wmat,
                                                        nullptr, out1_b, bufB, nullptr, nullptr,
                                                        eps2, bufA, 13);
    }
    // ---------- layer 2 ----------
    {
        int etot4 = EE * (DD / 4);
        scatter_add4_kernel<<<ceil_div(etot4, 256), 256>>>(bufB, src, dst, bufA);
        convert_kernel<<<ceil_div(cv_tot, 256), 256>>>(bufA, DD, p0h, p0l);
        gemm_hmma_kernel<0><<<ggrid, GTHREADS, GSMEM>>>(p0h, p0l, whi + 2 * wmat, wlo + 2 * wmat,
                                                        alpha2, beta2, nullptr, p1h, p1l,
                                                        nullptr, nullptr, 13);
        gemm_hmma_kernel<0><<<ggrid, GTHREADS, GSMEM>>>(p1h, p1l, whi + 3 * wmat, wlo + 3 * wmat,
                                                        nullptr, mlp2_b2, nullptr, p0h, p0l,
                                                        nullptr, nullptr, 13);
        gemm_hmma_kernel<1><<<ggrid, GTHREADS, GSMEM>>>(p0h, p0l, whi + 5 * wmat, wlo + 5 * wmat,
                                                        nullptr, out2_b, bufB, nullptr, nullptr,
                                                        eps3, bufA, 13);
    }
    // ---------- layer 3 ----------
    {
        int etot4 = EE * (DD / 4);
        scatter_add4_kernel<<<ceil_div(etot4, 256), 256>>>(bufB, src, dst, bufA);
        convert_kernel<<<ceil_div(cv_tot, 256), 256>>>(bufA, DD, p0h, p0l);
        gemm_hmma_kernel<0><<<ggrid, GTHREADS, GSMEM>>>(p0h, p0l, whi + 2 * wmat, wlo + 2 * wmat,
                                                        alpha2, beta2, nullptr, p1h, p1l,
                                                        nullptr, nullptr, 13);
        gemm_hmma_kernel<0><<<ggrid, GTHREADS, GSMEM>>>(p1h, p1l, whi + 3 * wmat, wlo + 3 * wmat,
                                                        nullptr, mlp2_b2, nullptr, p0h, p0l,
                                                        nullptr, nullptr, 13);
        gemm_hmma_kernel<1><<<ggrid, GTHREADS, GSMEM>>>(p0h, p0l, whi + 6 * wmat, wlo + 6 * wmat,
                                                        nullptr, out3_b, bufB, nullptr, nullptr,
                                                        nullptr, nullptr, 13);
    }
    // ---------- pooling + output ----------
    pool_out_kernel<<<GG, 256>>>(bufB, batch, out_w, out_b, out);
    (void)n_in; (void)out_size;
}

// round 6
// speedup vs baseline: 3.1748x; 1.2479x over previous
#include <cuda_runtime.h>
#include <cuda_fp16.h>
#include <cstdint>
#include <math.h>

// ================= problem constants =================
#define NN    50000
#define EE    400000
#define GG    256
#define FIN   79
#define DD    400
#define BN_EPS 1e-5f

#define NMATS  7
#define WPITCH 416            // staged weight K pitch (halfs)
#define PITCH  416            // fp32 activation pitch (13 * 32)
#define XPITCH 96             // layer-1 fp32 pitch (3 * 32)

// ================= scratch (device globals; zero-initialized) ============
__device__ float g_bufA[(size_t)NN * PITCH];
__device__ float g_bufB[(size_t)NN * PITCH];
__device__ float g_bufC[(size_t)NN * PITCH];
__device__ float g_xpad[(size_t)NN * XPITCH];
__device__ float g_z1[(size_t)NN * XPITCH];
__device__ __align__(16) __half g_Wh[(size_t)NMATS * DD * WPITCH];
__device__ float g_alpha1[DD], g_beta1[DD], g_alpha2[DD], g_beta2[DD];

// ================= helpers =================
__device__ __forceinline__ uint32_t smem_to_u32(const void* p) {
    uint32_t a;
    asm("{ .reg .u64 t; cvta.to.shared.u64 t, %1; cvt.u32.u64 %0, t; }"
        : "=r"(a) : "l"(p));
    return a;
}

// cp.async 16B; src-size 0 => zero-fill (used for OOB rows)
__device__ __forceinline__ void cp16(uint32_t saddr, const void* gptr, bool valid) {
    int sz = valid ? 16 : 0;
    asm volatile("cp.async.cg.shared.global [%0], [%1], 16, %2;"
                 :: "r"(saddr), "l"(gptr), "r"(sz));
}
#define CP_COMMIT() asm volatile("cp.async.commit_group;")
#define CP_WAIT(n)  asm volatile("cp.async.wait_group %0;" :: "n"(n))

#define LDSM4(R, addr) \
    asm volatile("ldmatrix.sync.aligned.m8n8.x4.shared.b16 {%0,%1,%2,%3}, [%4];" \
        : "=r"((R)[0]), "=r"((R)[1]), "=r"((R)[2]), "=r"((R)[3]) : "r"(addr))

#define LDSM2(R, addr) \
    asm volatile("ldmatrix.sync.aligned.m8n8.x2.shared.b16 {%0,%1}, [%2];" \
        : "=r"((R)[0]), "=r"((R)[1]) : "r"(addr))

__device__ __forceinline__ void mma_f16(float* d, const uint32_t* a, const uint32_t* b) {
    asm volatile(
        "mma.sync.aligned.m16n8k16.row.col.f32.f16.f16.f32 "
        "{%0,%1,%2,%3}, {%4,%5,%6,%7}, {%8,%9}, {%0,%1,%2,%3};"
        : "+f"(d[0]), "+f"(d[1]), "+f"(d[2]), "+f"(d[3])
        : "r"(a[0]), "r"(a[1]), "r"(a[2]), "r"(a[3]), "r"(b[0]), "r"(b[1]));
}

__device__ __forceinline__ uint32_t pack_h2(__half x, __half y) {
    return ((uint32_t)*(uint16_t*)&y << 16) | *(uint16_t*)&x;
}

__device__ __forceinline__ void red_add_v4(float* p, float4 v) {
    asm volatile("red.global.add.v4.f32 [%0], {%1, %2, %3, %4};"
                 :: "l"(p), "f"(v.x), "f"(v.y), "f"(v.z), "f"(v.w) : "memory");
}

// ================= fused setup kernel =================
// tasks: [0, T1)              : stage W as fp16 [mat][n][k<WPITCH]
//        [T1, T1+800)         : fold BN alpha/beta
//        [T1+800, +NN*48)     : zero pad columns [400,416) of bufA/bufB/bufC
#define T1 (NMATS * DD * WPITCH)
#define SETUP_TOTAL (T1 + 800 + NN * 48)

__global__ void setup_kernel(
    const float* __restrict__ w0, const float* __restrict__ w1,
    const float* __restrict__ w2, const float* __restrict__ w3,
    const float* __restrict__ w4, const float* __restrict__ w5,
    const float* __restrict__ w6,
    const float* __restrict__ b1a, const float* __restrict__ g1,
    const float* __restrict__ bb1, const float* __restrict__ m1,
    const float* __restrict__ v1,
    const float* __restrict__ b1b, const float* __restrict__ g2,
    const float* __restrict__ bb2, const float* __restrict__ m2,
    const float* __restrict__ v2) {
    int idx = blockIdx.x * blockDim.x + threadIdx.x;
    if (idx < T1) {
        const int per_mat = DD * WPITCH;
        int m = idx / per_mat;
        int r = idx - m * per_mat;
        int n = r / WPITCH;
        int k = r - n * WPITCH;
        int Km = (m == 0) ? FIN : DD;
        const float* W;
        switch (m) {
            case 0: W = w0; break; case 1: W = w1; break; case 2: W = w2; break;
            case 3: W = w3; break; case 4: W = w4; break; case 5: W = w5; break;
            default: W = w6; break;
        }
        float val = (k < Km) ? W[(size_t)k * DD + n] : 0.0f;
        g_Wh[idx] = __float2half(val);
    } else if (idx < T1 + 800) {
        int j = idx - T1;
        if (j < DD) {
            float a = g1[j] * rsqrtf(v1[j] + BN_EPS);
            g_alpha1[j] = a;
            g_beta1[j]  = (b1a[j] - m1[j]) * a + bb1[j];
        } else {
            int c = j - DD;
            float a = g2[c] * rsqrtf(v2[c] + BN_EPS);
            g_alpha2[c] = a;
            g_beta2[c]  = (b1b[c] - m2[c]) * a + bb2[c];
        }
    } else if (idx < SETUP_TOTAL) {
        int j = idx - T1 - 800;
        int row = j / 48;
        int t = j - row * 48;
        if (t < 16)      g_bufA[(size_t)row * PITCH + DD + t] = 0.0f;
        else if (t < 32) g_bufB[(size_t)row * PITCH + DD + (t - 16)] = 0.0f;
        else             g_bufC[(size_t)row * PITCH + DD + (t - 32)] = 0.0f;
    }
}

// ================= layer-1 glue =================

// x [NN][79] -> xpad [NN][96] (zeros beyond 79) and z1 = (1+eps1)*xpad
__global__ void pad_scale_kernel(const float* __restrict__ x,
                                 const float* __restrict__ eps) {
    int idx = blockIdx.x * blockDim.x + threadIdx.x;
    if (idx >= NN * XPITCH) return;
    int row = idx / XPITCH;
    int col = idx - row * XPITCH;
    float v = (col < FIN) ? x[(size_t)row * FIN + col] : 0.0f;
    g_xpad[idx] = v;
    g_z1[idx]   = (1.0f + eps[0]) * v;
}

// layer-1 scatter: 24 quarters of the 96-col padded plane
__global__ void scatter_add_x_kernel(const int* __restrict__ src,
                                     const int* __restrict__ dst) {
    int idx = blockIdx.x * blockDim.x + threadIdx.x;
    if (idx >= EE * (XPITCH / 4)) return;
    int e = idx / (XPITCH / 4);
    int q = idx - e * (XPITCH / 4);
    const float4 v = *(const float4*)(g_xpad + (size_t)src[e] * XPITCH + q * 4);
    red_add_v4(g_z1 + (size_t)dst[e] * XPITCH + q * 4, v);
}

// D=400 scatter on PITCH-416 buffers (only first 100 quarters carry data)
__global__ void scatter_add4_kernel(const float* __restrict__ h,
                                    const int* __restrict__ src,
                                    const int* __restrict__ dst,
                                    float* __restrict__ z) {
    int idx = blockIdx.x * blockDim.x + threadIdx.x;
    if (idx >= EE * (DD / 4)) return;
    int e = idx / (DD / 4);
    int q = idx - e * (DD / 4);
    const float4 v = *(const float4*)(h + (size_t)src[e] * PITCH + q * 4);
    red_add_v4(z + (size_t)dst[e] * PITCH + q * 4, v);
}

// ================= HMMA GEMM: fp32 A split in-smem to fp16 hi/lo ============
// C[n x 400] = act( alpha .* (A @ W) + beta ); W as single fp16 plane.
// Products: Ah*W + Al*W  (== exact-A x fp16 weights)
// MODE 0: relu -> fp32 Cf.  MODE 1: tanh -> fp32 Cf (+ optional (1+eps)*tanh -> Zinit)
// INVARIANT: A, Cf, Zinit must be pairwise-distinct buffers (cross-CTA race otherwise).
#define BM 128
#define BN 200
#define GTHREADS 640
#define ST_AF 0                    // fp32 A tile: 128 rows * 144B = 18432
#define ST_AH 18432                // fp16 hi plane: 128 * 80B = 10240
#define ST_AL 28672                // fp16 lo plane: 10240
#define ST_BH 38912                // fp16 W tile: 200 * 80B = 16000
#define STAGE_BYTES 54912
#define GSMEM (2 * STAGE_BYTES)    // 109824

__device__ __forceinline__ void load_stage(
    uint32_t sbase,
    const float* __restrict__ A, int lda,
    const __half* __restrict__ Wh,
    int m0, int n0, int kb, int tid) {
    int k0 = kb * 32;
#pragma unroll 1
    for (int id = tid; id < 1824; id += GTHREADS) {
        if (id < 1024) {
            int row = id >> 3, ch = id & 7;
            int gr = m0 + row;
            bool valid = gr < NN;
            size_t goff = valid ? ((size_t)gr * lda + k0 + ch * 4) : 0;
            cp16(sbase + ST_AF + row * 144 + ch * 16, A + goff, valid);
        } else {
            int id2 = id - 1024;
            int row = id2 >> 2, ch = id2 & 3;
            size_t goff = (size_t)(n0 + row) * WPITCH + k0 + ch * 8;
            cp16(sbase + ST_BH + row * 80 + ch * 16, Wh + goff, true);
        }
    }
}

template <int MODE>
__global__ __launch_bounds__(GTHREADS, 1) void gemm_hmma_kernel(
    const float* __restrict__ A, int lda, int kblks,
    const __half* __restrict__ Wh,
    const float* __restrict__ alpha, const float* __restrict__ beta,
    float* __restrict__ Cf,
    const float* __restrict__ epsn, float* __restrict__ Zinit) {
    extern __shared__ char smem[];
    uint32_t sb = smem_to_u32(smem);
    int tid  = threadIdx.x;
    int wid  = tid >> 5;
    int lane = tid & 31;
    int wm = wid / 5;            // 0..3
    int wn = wid - wm * 5;       // 0..4
    int m0 = blockIdx.x * BM;
    int n0 = blockIdx.y * BN;

    float acc[2][5][4];
#pragma unroll
    for (int i = 0; i < 2; i++)
#pragma unroll
        for (int j = 0; j < 5; j++)
#pragma unroll
            for (int k = 0; k < 4; k++) acc[i][j][k] = 0.0f;

    load_stage(sb, A, lda, Wh, m0, n0, 0, tid);
    CP_COMMIT();

#pragma unroll 1
    for (int kb = 0; kb < kblks; kb++) {
        if (kb + 1 < kblks) {
            load_stage(sb + ((kb + 1) & 1) * STAGE_BYTES, A, lda, Wh, m0, n0, kb + 1, tid);
            CP_COMMIT();
            CP_WAIT(1);
        } else {
            CP_WAIT(0);
        }
        __syncthreads();

        char* sm = smem + (kb & 1) * STAGE_BYTES;
        uint32_t sbase = sb + (kb & 1) * STAGE_BYTES;

        // ---- split fp32 A tile into fp16 hi/lo planes ----
        if (tid < 512) {
            int row = tid >> 2, ch = tid & 3;
            const float4 v0 = *(const float4*)(sm + ST_AF + row * 144 + ch * 32);
            const float4 v1 = *(const float4*)(sm + ST_AF + row * 144 + ch * 32 + 16);
            float f[8] = {v0.x, v0.y, v0.z, v0.w, v1.x, v1.y, v1.z, v1.w};
            uint32_t hp[4], lp[4];
#pragma unroll
            for (int j = 0; j < 4; j++) {
                __half h0 = __float2half(f[2 * j]);
                __half h1 = __float2half(f[2 * j + 1]);
                __half l0 = __float2half(f[2 * j]     - __half2float(h0));
                __half l1 = __float2half(f[2 * j + 1] - __half2float(h1));
                hp[j] = pack_h2(h0, h1);
                lp[j] = pack_h2(l0, l1);
            }
            *(uint4*)(sm + ST_AH + row * 80 + ch * 16) = make_uint4(hp[0], hp[1], hp[2], hp[3]);
            *(uint4*)(sm + ST_AL + row * 80 + ch * 16) = make_uint4(lp[0], lp[1], lp[2], lp[3]);
        }
        __syncthreads();

        // ---- MMA over this k-block (two k=16 slices) ----
#pragma unroll
        for (int kk = 0; kk < 2; kk++) {
            uint32_t af[2][2][4];   // [plane][mtile][4]
#pragma unroll
            for (int mt = 0; mt < 2; mt++) {
                uint32_t row  = wm * 32 + mt * 16 + (lane & 15);
                uint32_t addr = sbase + ST_AH + row * 80 + kk * 32 + ((lane >> 4) << 4);
                LDSM4(af[0][mt], addr);
                LDSM4(af[1][mt], addr + (ST_AL - ST_AH));
            }
            uint32_t bfr[5][2];
#pragma unroll
            for (int nt = 0; nt < 5; nt++) {
                uint32_t row  = wn * 40 + nt * 8 + (lane & 7);
                uint32_t addr = sbase + ST_BH + row * 80 + kk * 32 + (((lane >> 3) & 1) << 4);
                LDSM2(bfr[nt], addr);
            }
#pragma unroll
            for (int mt = 0; mt < 2; mt++)
#pragma unroll
                for (int nt = 0; nt < 5; nt++) {
                    mma_f16(acc[mt][nt], af[0][mt], bfr[nt]);  // Ah * W
                    mma_f16(acc[mt][nt], af[1][mt], bfr[nt]);  // Al * W
                }
        }
        __syncthreads();
    }

    // ---------------- epilogue ----------------
    float sc = (MODE == 1 && Zinit) ? (1.0f + epsn[0]) : 0.0f;
#pragma unroll
    for (int mt = 0; mt < 2; mt++) {
#pragma unroll
        for (int nt = 0; nt < 5; nt++) {
            int c  = n0 + wn * 40 + nt * 8 + (lane & 3) * 2;
            int r0 = m0 + wm * 32 + mt * 16 + (lane >> 2);
            float a0 = alpha ? alpha[c]     : 1.0f;
            float a1 = alpha ? alpha[c + 1] : 1.0f;
            float b0 = beta[c], b1 = beta[c + 1];
            float v00 = acc[mt][nt][0] * a0 + b0;
            float v01 = acc[mt][nt][1] * a1 + b1;
            float v10 = acc[mt][nt][2] * a0 + b0;
            float v11 = acc[mt][nt][3] * a1 + b1;
            if (MODE == 0) {
                if (r0 < NN)
                    *(float2*)(Cf + (size_t)r0 * PITCH + c) =
                        make_float2(fmaxf(v00, 0.f), fmaxf(v01, 0.f));
                if (r0 + 8 < NN)
                    *(float2*)(Cf + (size_t)(r0 + 8) * PITCH + c) =
                        make_float2(fmaxf(v10, 0.f), fmaxf(v11, 0.f));
            } else {
                float t00 = tanhf(v00), t01 = tanhf(v01);
                float t10 = tanhf(v10), t11 = tanhf(v11);
                if (r0 < NN) {
                    *(float2*)(Cf + (size_t)r0 * PITCH + c) = make_float2(t00, t01);
                    if (Zinit)
                        *(float2*)(Zinit + (size_t)r0 * PITCH + c) =
                            make_float2(sc * t00, sc * t01);
                }
                if (r0 + 8 < NN) {
                    *(float2*)(Cf + (size_t)(r0 + 8) * PITCH + c) = make_float2(t10, t11);
                    if (Zinit)
                        *(float2*)(Zinit + (size_t)(r0 + 8) * PITCH + c) =
                            make_float2(sc * t10, sc * t11);
                }
            }
        }
    }
}

// ================= pooling + final projection (atomic-free) =================

__device__ __forceinline__ int lower_bound_batch(const int* __restrict__ b, int val) {
    int lo = 0, hi = NN;
    while (lo < hi) {
        int mid = (lo + hi) >> 1;
        if (b[mid] < val) lo = mid + 1; else hi = mid;
    }
    return lo;
}

__global__ __launch_bounds__(256) void pool_out_kernel(
    const float* __restrict__ h, const int* __restrict__ batch,
    const float* __restrict__ w, const float* __restrict__ b,
    float* __restrict__ out) {
    int g   = blockIdx.x;
    int tid = threadIdx.x;
    int lo = lower_bound_batch(batch, g);
    int hi = lower_bound_batch(batch, g + 1);
    float invc = 1.0f / fmaxf((float)(hi - lo), 1.0f);
    float part = 0.0f;
    for (int f = tid; f < DD; f += 256) {
        float mx = -INFINITY, sm = 0.0f;
        for (int node = lo; node < hi; node++) {
            float v = h[(size_t)node * PITCH + f];
            mx = fmaxf(mx, v);
            sm += v;
        }
        if (hi == lo) mx = 0.0f;
        part += mx * w[f] + sm * invc * w[DD + f];
    }
#pragma unroll
    for (int o = 16; o > 0; o >>= 1) part += __shfl_down_sync(0xffffffffu, part, o);
    __shared__ float sh[8];
    if ((tid & 31) == 0) sh[tid >> 5] = part;
    __syncthreads();
    if (tid == 0) {
        float t = 0.0f;
#pragma unroll
        for (int i = 0; i < 8; i++) t += sh[i];
        out[g] = t + b[0];
    }
}

// ================= host orchestration =================

static inline int ceil_div(int a, int b) { return (a + b - 1) / b; }

extern "C" void kernel_launch(void* const* d_in, const int* in_sizes, int n_in,
                              void* d_out, int out_size) {
    const float* x     = (const float*)d_in[0];
    const int*   ei    = (const int*)d_in[1];
    const int*   src   = ei;
    const int*   dst   = ei + EE;
    const int*   batch = (const int*)d_in[2];
    int base = (in_sizes[3] == 1) ? 4 : 3;

    const float* mlp1_w1   = (const float*)d_in[base + 0];
    const float* mlp1_b1   = (const float*)d_in[base + 1];
    const float* mlp1_bn_g = (const float*)d_in[base + 2];
    const float* mlp1_bn_b = (const float*)d_in[base + 3];
    const float* mlp1_bn_m = (const float*)d_in[base + 4];
    const float* mlp1_bn_v = (const float*)d_in[base + 5];
    const float* mlp1_w2   = (const float*)d_in[base + 6];
    const float* mlp1_b2   = (const float*)d_in[base + 7];
    const float* mlp2_w1   = (const float*)d_in[base + 8];
    const float* mlp2_b1   = (const float*)d_in[base + 9];
    const float* mlp2_bn_g = (const float*)d_in[base + 10];
    const float* mlp2_bn_b = (const float*)d_in[base + 11];
    const float* mlp2_bn_m = (const float*)d_in[base + 12];
    const float* mlp2_bn_v = (const float*)d_in[base + 13];
    const float* mlp2_w2   = (const float*)d_in[base + 14];
    const float* mlp2_b2   = (const float*)d_in[base + 15];
    const float* out1_w    = (const float*)d_in[base + 16];
    const float* out1_b    = (const float*)d_in[base + 17];
    const float* out2_w    = (const float*)d_in[base + 18];
    const float* out2_b    = (const float*)d_in[base + 19];
    const float* out3_w    = (const float*)d_in[base + 20];
    const float* out3_b    = (const float*)d_in[base + 21];
    const float* out_w     = (const float*)d_in[base + 22];
    const float* out_b     = (const float*)d_in[base + 23];
    const float* eps1      = (const float*)d_in[base + 24];
    const float* eps2      = (const float*)d_in[base + 25];
    const float* eps3      = (const float*)d_in[base + 26];

    float* out = (float*)d_out;

    float *bufA, *bufB, *bufC, *z1, *alpha1, *beta1, *alpha2, *beta2;
    __half* wh;
    cudaGetSymbolAddress((void**)&bufA, g_bufA);
    cudaGetSymbolAddress((void**)&bufB, g_bufB);
    cudaGetSymbolAddress((void**)&bufC, g_bufC);
    cudaGetSymbolAddress((void**)&z1,   g_z1);
    cudaGetSymbolAddress((void**)&alpha1, g_alpha1);
    cudaGetSymbolAddress((void**)&beta1,  g_beta1);
    cudaGetSymbolAddress((void**)&alpha2, g_alpha2);
    cudaGetSymbolAddress((void**)&beta2,  g_beta2);
    cudaGetSymbolAddress((void**)&wh, g_Wh);

    cudaFuncSetAttribute(gemm_hmma_kernel<0>,
                         cudaFuncAttributeMaxDynamicSharedMemorySize, GSMEM);
    cudaFuncSetAttribute(gemm_hmma_kernel<1>,
                         cudaFuncAttributeMaxDynamicSharedMemorySize, GSMEM);

    dim3 ggrid(ceil_div(NN, BM), 2);   // (391, 2)
    size_t wmat = (size_t)DD * WPITCH;

    // 1: fused setup (W fp16 staging, BN fold, pad-column zeroing)
    setup_kernel<<<ceil_div(SETUP_TOTAL, 256), 256>>>(
        mlp1_w1, mlp1_w2, mlp2_w1, mlp2_w2, out1_w, out2_w, out3_w,
        mlp1_b1, mlp1_bn_g, mlp1_bn_b, mlp1_bn_m, mlp1_bn_v,
        mlp2_b1, mlp2_bn_g, mlp2_bn_b, mlp2_bn_m, mlp2_bn_v);

    // ---------- layer 1 ----------
    pad_scale_kernel<<<ceil_div(NN * XPITCH, 256), 256>>>(x, eps1);
    scatter_add_x_kernel<<<ceil_div(EE * (XPITCH / 4), 256), 256>>>(src, dst);
    gemm_hmma_kernel<0><<<ggrid, GTHREADS, GSMEM>>>(z1, XPITCH, 3, wh + 0 * wmat,
                                                    alpha1, beta1, bufA, nullptr, nullptr);
    gemm_hmma_kernel<0><<<ggrid, GTHREADS, GSMEM>>>(bufA, PITCH, 13, wh + 1 * wmat,
                                                    nullptr, mlp1_b2, bufB, nullptr, nullptr);
    // tanh: h1 -> bufA, (1+eps2)*h1 -> bufC   (A=bufB distinct from both)
    gemm_hmma_kernel<1><<<ggrid, GTHREADS, GSMEM>>>(bufB, PITCH, 13, wh + 4 * wmat,
                                                    nullptr, out1_b, bufA, eps2, bufC);
    // ---------- layer 2 ----------
    scatter_add4_kernel<<<ceil_div(EE * (DD / 4), 256), 256>>>(bufA, src, dst, bufC);
    gemm_hmma_kernel<0><<<ggrid, GTHREADS, GSMEM>>>(bufC, PITCH, 13, wh + 2 * wmat,
                                                    alpha2, beta2, bufB, nullptr, nullptr);
    gemm_hmma_kernel<0><<<ggrid, GTHREADS, GSMEM>>>(bufB, PITCH, 13, wh + 3 * wmat,
                                                    nullptr, mlp2_b2, bufA, nullptr, nullptr);
    // tanh: h2 -> bufB, (1+eps3)*h2 -> bufC   (A=bufA distinct from both)
    gemm_hmma_kernel<1><<<ggrid, GTHREADS, GSMEM>>>(bufA, PITCH, 13, wh + 5 * wmat,
                                                    nullptr, out2_b, bufB, eps3, bufC);
    // ---------- layer 3 ----------
    scatter_add4_kernel<<<ceil_div(EE * (DD / 4), 256), 256>>>(bufB, src, dst, bufC);
    gemm_hmma_kernel<0><<<ggrid, GTHREADS, GSMEM>>>(bufC, PITCH, 13, wh + 2 * wmat,
                                                    alpha2, beta2, bufA, nullptr, nullptr);
    gemm_hmma_kernel<0><<<ggrid, GTHREADS, GSMEM>>>(bufA, PITCH, 13, wh + 3 * wmat,
                                                    nullptr, mlp2_b2, bufB, nullptr, nullptr);
    gemm_hmma_kernel<1><<<ggrid, GTHREADS, GSMEM>>>(bufB, PITCH, 13, wh + 6 * wmat,
                                                    nullptr, out3_b, bufA, nullptr, nullptr);
    // ---------- pooling + output ----------
    pool_out_kernel<<<GG, 256>>>(bufA, batch, out_w, out_b, out);
    (void)n_in; (void)out_size;
}